// round 13
// baseline (speedup 1.0000x reference)
#include <cuda_runtime.h>

// CombPool2d: out = (w_avg^2)*avg_pool2x2(x) + (w_max^2)*max_pool2x2(x)
// x: (16,192,224,224) f32, w_avg/w_max: (1,192,1,1), out: (16,192,112,112)
//
// HBM-bound streaming kernel (~771 MB). R2/R4/R5/R9 all converge at
// ~7.05-7.11 TB/s (~89% DRAM cycles) across four different instruction mixes
// -> DRAM-subsystem ceiling. R10: persistent grid-stride variant — single
// wave of CTAs, each looping over ~31 quads, keeping every SM's load queue
// continuously primed (no per-block prologue/retire churn across 254 waves).
// Per-iteration body identical to R5: 2x LDG.256 -> 4 outputs -> 1x STG.128.

#define IH 224
#define IW 224
#define OH 112
#define OW 112
#define C_CH 192
#define EW (IW / 8)          // 28 8-float chunks per input row

__global__ void __launch_bounds__(256)
combpool2d_kernel(const float* __restrict__ x,
                  const float* __restrict__ w_avg,
                  const float* __restrict__ w_max,
                  float* __restrict__ out,
                  int total)
{
    int stride = gridDim.x * blockDim.x;

    for (int i = blockIdx.x * blockDim.x + threadIdx.x; i < total; i += stride) {
        // i -> (bc, oh, ew) with compile-time-constant divisors
        int ew = i % EW;
        int t  = i / EW;
        int oh = t % OH;
        int bc = t / OH;           // fused batch*channel, 0..3071
        int c  = bc % C_CH;

        float wa = __ldg(w_avg + c);
        float wm = __ldg(w_max + c);
        wa = wa * wa * 0.25f;      // fold 1/(K*K) into the avg coefficient
        wm = wm * wm;

        const float* r0 = x + (size_t)bc * (IH * IW) + (size_t)(2 * oh) * IW + ew * 8;
        const float* r1 = r0 + IW;

        // Two 256-bit loads: 8 floats from each input row (32B, 32B-aligned).
        float a0, a1, a2, a3, a4, a5, a6, a7;
        float b0, b1, b2, b3, b4, b5, b6, b7;
        asm volatile("ld.global.nc.v8.f32 {%0,%1,%2,%3,%4,%5,%6,%7}, [%8];"
                     : "=f"(a0), "=f"(a1), "=f"(a2), "=f"(a3),
                       "=f"(a4), "=f"(a5), "=f"(a6), "=f"(a7)
                     : "l"(r0));
        asm volatile("ld.global.nc.v8.f32 {%0,%1,%2,%3,%4,%5,%6,%7}, [%8];"
                     : "=f"(b0), "=f"(b1), "=f"(b2), "=f"(b3),
                       "=f"(b4), "=f"(b5), "=f"(b6), "=f"(b7)
                     : "l"(r1));

        float4 o;
        o.x = wa * (a0 + a1 + b0 + b1) + wm * fmaxf(fmaxf(a0, a1), fmaxf(b0, b1));
        o.y = wa * (a2 + a3 + b2 + b3) + wm * fmaxf(fmaxf(a2, a3), fmaxf(b2, b3));
        o.z = wa * (a4 + a5 + b4 + b5) + wm * fmaxf(fmaxf(a4, a5), fmaxf(b4, b5));
        o.w = wa * (a6 + a7 + b6 + b7) + wm * fmaxf(fmaxf(a6, a7), fmaxf(b6, b7));

        *reinterpret_cast<float4*>(
            out + (size_t)bc * (OH * OW) + (size_t)oh * OW + ew * 4) = o;
    }
}

extern "C" void kernel_launch(void* const* d_in, const int* in_sizes, int n_in,
                              void* d_out, int out_size)
{
    const float* x     = (const float*)d_in[0];
    const float* w_avg = (const float*)d_in[1];
    const float* w_max = (const float*)d_in[2];
    float* out = (float*)d_out;

    int total = out_size / 4;                     // 9,633,792 quads
    // Single persistent wave: ~6 CTAs/SM at regs~32, 148 SMs (152 on GB300).
    int blocks = 152 * 6;
    combpool2d_kernel<<<blocks, 256>>>(x, w_avg, w_max, out, total);
}

// round 14
// speedup vs baseline: 1.0590x; 1.0590x over previous
#include <cuda_runtime.h>

// CombPool2d: out = (w_avg^2)*avg_pool2x2(x) + (w_max^2)*max_pool2x2(x)
// x: (16,192,224,224) f32, w_avg/w_max: (1,192,1,1), out: (16,192,112,112)
//
// HBM-bound streaming kernel (~771 MB, floor ~96us @ 8TB/s spec).
// Flat-launch R2/R5/R9 all converge at ~7.05-7.11 TB/s (~89% DRAM cycles);
// software persistence (R10) regressed. R13 isolates the last untested
// variable: evict-first STORE policy (__stcs) on the write stream, which is
// the only knob touching the read/write interleave at the LTS->DRAM boundary.
// Body otherwise identical to R5: 2x LDG.256 -> 4 outputs -> 1x STG.128.

#define IH 224
#define IW 224
#define OH 112
#define OW 112
#define C_CH 192
#define EW (IW / 8)          // 28 8-float chunks per input row

__global__ void __launch_bounds__(256)
combpool2d_kernel(const float* __restrict__ x,
                  const float* __restrict__ w_avg,
                  const float* __restrict__ w_max,
                  float* __restrict__ out,
                  int total)
{
    int i = blockIdx.x * blockDim.x + threadIdx.x;
    if (i >= total) return;

    // i -> (bc, oh, ew) with compile-time-constant divisors
    int ew = i % EW;
    int t  = i / EW;
    int oh = t % OH;
    int bc = t / OH;           // fused batch*channel, 0..3071
    int c  = bc % C_CH;

    float wa = __ldg(w_avg + c);
    float wm = __ldg(w_max + c);
    wa = wa * wa * 0.25f;      // fold 1/(K*K) into the avg coefficient
    wm = wm * wm;

    const float* r0 = x + (size_t)bc * (IH * IW) + (size_t)(2 * oh) * IW + ew * 8;
    const float* r1 = r0 + IW;

    // Two 256-bit loads: 8 floats from each input row (32B, 32B-aligned).
    float a0, a1, a2, a3, a4, a5, a6, a7;
    float b0, b1, b2, b3, b4, b5, b6, b7;
    asm volatile("ld.global.nc.v8.f32 {%0,%1,%2,%3,%4,%5,%6,%7}, [%8];"
                 : "=f"(a0), "=f"(a1), "=f"(a2), "=f"(a3),
                   "=f"(a4), "=f"(a5), "=f"(a6), "=f"(a7)
                 : "l"(r0));
    asm volatile("ld.global.nc.v8.f32 {%0,%1,%2,%3,%4,%5,%6,%7}, [%8];"
                 : "=f"(b0), "=f"(b1), "=f"(b2), "=f"(b3),
                   "=f"(b4), "=f"(b5), "=f"(b6), "=f"(b7)
                 : "l"(r1));

    float4 o;
    o.x = wa * (a0 + a1 + b0 + b1) + wm * fmaxf(fmaxf(a0, a1), fmaxf(b0, b1));
    o.y = wa * (a2 + a3 + b2 + b3) + wm * fmaxf(fmaxf(a2, a3), fmaxf(b2, b3));
    o.z = wa * (a4 + a5 + b4 + b5) + wm * fmaxf(fmaxf(a4, a5), fmaxf(b4, b5));
    o.w = wa * (a6 + a7 + b6 + b7) + wm * fmaxf(fmaxf(a6, a7), fmaxf(b6, b7));

    // Evict-first 128-bit store: output has zero reuse, keep it from
    // competing with the read stream for L2 residency / writeback timing.
    __stcs(reinterpret_cast<float4*>(
        out + (size_t)bc * (OH * OW) + (size_t)oh * OW + ew * 4), o);
}

extern "C" void kernel_launch(void* const* d_in, const int* in_sizes, int n_in,
                              void* d_out, int out_size)
{
    const float* x     = (const float*)d_in[0];
    const float* w_avg = (const float*)d_in[1];
    const float* w_max = (const float*)d_in[2];
    float* out = (float*)d_out;

    int total = out_size / 4;                     // 9,633,792 threads
    int threads = 256;
    int blocks = (total + threads - 1) / threads;
    combpool2d_kernel<<<blocks, threads>>>(x, w_avg, w_max, out, total);
}